// round 3
// baseline (speedup 1.0000x reference)
#include <cuda_runtime.h>
#include <cstdint>

// CSCFCLayer: out[b][n] = sum_{f<64} x[b][(n+f)%C] * kernel[(n+f)%C][n] + bias[n]
// B=128, C=N=8192, F=64, fp32.
//
// v3: grid=256 (128 col-tiles x 2 batch-halves), 512 threads, 2 CTAs/SM (50% occ).
//  - Per CTA: 64 output cols, 64 batches. ws plain fp32 (32KB), xs batch-paired (33KB).
//  - cp.async fills (pre-zeroed ws + contiguous band-range copies; scattered 4B x copies).
//  - Inner loop: LDS.64 x-pair + 2x LDS.128 w + 8 mov-pack + 8 fma.rn.f32x2.
//  - Epilogue: 2-way partial reduce through smem, coalesced stores + bias.

#define CDIM 8192
#define NDIM 8192
#define NT 64
#define BT 64                  // batches per CTA
#define THREADS 512
#define NWARPS 16
#define CROWS 128
#define WS_STRIDE 64           // floats per ws row
#define XS_STRIDE 66           // floats per xs row (33 float2)
#define HALF_STEPS 36

__device__ __forceinline__ void fma2(unsigned long long& d,
                                     unsigned long long a,
                                     unsigned long long b) {
    asm("fma.rn.f32x2 %0, %1, %2, %0;" : "+l"(d) : "l"(a), "l"(b));
}

__device__ __forceinline__ unsigned long long dup2(float v) {
    unsigned long long r;
    unsigned u = __float_as_uint(v);
    asm("mov.b64 %0, {%1, %1};" : "=l"(r) : "r"(u));
    return r;
}

__device__ __forceinline__ void cpasync4(unsigned dst, const void* src) {
    asm volatile("cp.async.ca.shared.global [%0], [%1], 4;"
                 :: "r"(dst), "l"(src) : "memory");
}

extern "C" __global__ void __launch_bounds__(THREADS, 2)
cscfc_kernel(const float* __restrict__ x,
             const float* __restrict__ w,
             const float* __restrict__ bias,
             float* __restrict__ out)
{
    extern __shared__ float smem[];
    float* ws = smem;                          // CROWS * WS_STRIDE
    float* xs = smem + CROWS * WS_STRIDE;      // CROWS * XS_STRIDE

    const int tid  = threadIdx.x;
    const int lane = tid & 31;
    const int wid  = tid >> 5;
    const int ng   = wid & 7;                  // column group (8 cols)
    const int half = wid >> 3;                 // c-window half
    const int tile = blockIdx.x & 127;
    const int bh   = blockIdx.x >> 7;
    const int n0   = tile * NT;
    const int b0   = bh * BT;

    const unsigned ws_u = (unsigned)__cvta_generic_to_shared(ws);
    const unsigned xs_u = (unsigned)__cvta_generic_to_shared(xs);

    // ---- Pre-zero ws (band mask becomes implicit). ----
#pragma unroll
    for (int i = tid; i < CROWS * WS_STRIDE / 4; i += THREADS)
        ((float4*)ws)[i] = make_float4(0.f, 0.f, 0.f, 0.f);
    __syncthreads();

    // ---- xs fill via cp.async: xs[cl] pair q = (x[b0+q][c], x[b0+q+32][c]). ----
#pragma unroll
    for (int k = 0; k < 16; ++k) {
        const int idx = tid + k * THREADS;
        const int cl  = idx & 127;             // lanes vary cl -> coalesced gmem
        const int b   = idx >> 7;              // 0..63
        const int c   = (n0 + cl) & (CDIM - 1);
        const unsigned dst =
            xs_u + (unsigned)(cl * XS_STRIDE + (b & 31) * 2 + (b >> 5)) * 4u;
        cpasync4(dst, x + (size_t)(b0 + b) * CDIM + c);
    }

    // ---- ws fill via cp.async: per row cl, valid cols nl in [cl-63, cl] ∩ [0,64).
    //      Contiguous range, coalesced src reads. ----
    for (int cl = wid; cl < CROWS; cl += NWARPS) {
        const int r  = (n0 + cl) & (CDIM - 1);
        const int lo = (cl - 63 > 0) ? cl - 63 : 0;
        const int hi = (cl < 63) ? cl : 63;
        const float* wrow = w + (size_t)r * NDIM + n0;
        for (int nl = lo + lane; nl <= hi; nl += 32)
            cpasync4(ws_u + (unsigned)(cl * WS_STRIDE + nl) * 4u, wrow + nl);
    }
    asm volatile("cp.async.commit_group;" ::: "memory");
    asm volatile("cp.async.wait_group 0;" ::: "memory");
    __syncthreads();

    // ---- Compute: warp (ng, half): cols n0+ng*8..+7, 36 c-steps. ----
    unsigned long long acc[8];
#pragma unroll
    for (int j = 0; j < 8; ++j) acc[j] = 0ULL;

    const int cl0 = ng * 8 + half * HALF_STEPS;
    const float* xrow = xs + cl0 * XS_STRIDE + lane * 2;
    const float* wrow = ws + cl0 * WS_STRIDE + ng * 8;
#pragma unroll 4
    for (int i = 0; i < HALF_STEPS; ++i) {
        const unsigned long long xp = *(const unsigned long long*)xrow;  // (b, b+32)
        const float4 wa = *(const float4*)(wrow);       // LDS.128 broadcast
        const float4 wb = *(const float4*)(wrow + 4);
        fma2(acc[0], xp, dup2(wa.x));
        fma2(acc[1], xp, dup2(wa.y));
        fma2(acc[2], xp, dup2(wa.z));
        fma2(acc[3], xp, dup2(wa.w));
        fma2(acc[4], xp, dup2(wb.x));
        fma2(acc[5], xp, dup2(wb.y));
        fma2(acc[6], xp, dup2(wb.z));
        fma2(acc[7], xp, dup2(wb.w));
        xrow += XS_STRIDE;
        wrow += WS_STRIDE;
    }
    __syncthreads();

    // ---- Epilogue: reduce the two halves through smem, then coalesced stores. ----
    float* os = smem;   // [64 b][65] floats, aliases ws/xs
    if (half == 0) {
#pragma unroll
        for (int j = 0; j < 8; ++j) {
            const int nl = ng * 8 + j;
            os[lane * 65 + nl]        = __uint_as_float((unsigned)(acc[j] & 0xffffffffu));
            os[(lane + 32) * 65 + nl] = __uint_as_float((unsigned)(acc[j] >> 32));
        }
    }
    __syncthreads();
    if (half == 1) {
#pragma unroll
        for (int j = 0; j < 8; ++j) {
            const int nl = ng * 8 + j;
            os[lane * 65 + nl]        += __uint_as_float((unsigned)(acc[j] & 0xffffffffu));
            os[(lane + 32) * 65 + nl] += __uint_as_float((unsigned)(acc[j] >> 32));
        }
    }
    __syncthreads();

#pragma unroll
    for (int t = tid; t < BT * NT; t += THREADS) {   // 8 iters
        const int nl = t & (NT - 1);
        const int bl = t >> 6;
        out[(size_t)(b0 + bl) * NDIM + n0 + nl] = os[bl * 65 + nl] + bias[n0 + nl];
    }
}

extern "C" void kernel_launch(void* const* d_in, const int* in_sizes, int n_in,
                              void* d_out, int out_size) {
    const float* x    = (const float*)d_in[0];
    const float* w    = (const float*)d_in[1];
    const float* bias = (const float*)d_in[2];
    float* out        = (float*)d_out;

    const size_t smem_bytes =
        (size_t)(CROWS * WS_STRIDE + CROWS * XS_STRIDE) * sizeof(float);
    cudaFuncSetAttribute(cscfc_kernel,
                         cudaFuncAttributeMaxDynamicSharedMemorySize,
                         (int)smem_bytes);
    cscfc_kernel<<<256, THREADS, smem_bytes>>>(x, w, bias, out);
}